// round 6
// baseline (speedup 1.0000x reference)
#include <cuda_runtime.h>
#include <cuda_bf16.h>
#include <cstdint>

#define N_REL   32
#define N_BASES 30
#define IN_F    64
#define OUT_F   64
#define MAX_NODES 100000
#define MAX_EDGES 1000000
#define TE      128   // edges (rows) per tile

// ---------------- device scratch (static, allocation-free) ----------------
__device__ __nv_bfloat16  g_Wbf[N_REL * OUT_F * IN_F];   // bf16, TRANSPOSED: [r][o][i]
__device__ float g_deg[MAX_NODES];
__device__ float g_inv[MAX_NODES];
__device__ int   g_hist[N_REL];
__device__ int   g_commit[N_REL];
__device__ int   g_sorted[MAX_EDGES];

// ---------------- helpers ----------------
__device__ __forceinline__ uint32_t smem_u32(const void* p) {
    uint32_t a;
    asm("{ .reg .u64 t; cvta.to.shared.u64 t, %1; cvt.u32.u64 %0, t; }" : "=r"(a) : "l"(p));
    return a;
}
__device__ __forceinline__ uint32_t bf2pack(float lo, float hi) {
    uint32_t r;
    asm("cvt.rn.bf16x2.f32 %0, %1, %2;" : "=r"(r) : "f"(hi), "f"(lo));
    return r;
}
__device__ __forceinline__ void sts128(uint32_t addr, uint32_t a, uint32_t b, uint32_t c, uint32_t d) {
    asm volatile("st.shared.v4.b32 [%0], {%1, %2, %3, %4};" :: "r"(addr), "r"(a), "r"(b), "r"(c), "r"(d) : "memory");
}
__device__ __forceinline__ void red4(float* p, float a, float b, float c, float d) {
    asm volatile("red.global.add.v4.f32 [%0], {%1, %2, %3, %4};"
                 :: "l"(p), "f"(a), "f"(b), "f"(c), "f"(d) : "memory");
}
__device__ __forceinline__ unsigned long long f2pack(float lo, float hi) {
    unsigned long long r;
    asm("mov.b64 %0, {%1, %2};" : "=l"(r) : "f"(lo), "f"(hi));
    return r;
}
__device__ __forceinline__ void f2unpack(unsigned long long v, float& lo, float& hi) {
    asm("mov.b64 {%0, %1}, %2;" : "=f"(lo), "=f"(hi) : "l"(v));
}
__device__ __forceinline__ unsigned long long ffma2(unsigned long long a, unsigned long long b,
                                                    unsigned long long c) {
    unsigned long long d;
    asm("fma.rn.f32x2 %0, %1, %2, %3;" : "=l"(d) : "l"(a), "l"(b), "l"(c));
    return d;
}
__device__ __forceinline__ void ldm_x4(uint32_t& r0, uint32_t& r1, uint32_t& r2, uint32_t& r3,
                                       uint32_t addr) {
    asm volatile("ldmatrix.sync.aligned.m8n8.x4.shared.b16 {%0, %1, %2, %3}, [%4];"
                 : "=r"(r0), "=r"(r1), "=r"(r2), "=r"(r3) : "r"(addr));
}
__device__ __forceinline__ void mma_bf16(float* d, uint32_t a0, uint32_t a1, uint32_t a2,
                                         uint32_t a3, uint32_t b0, uint32_t b1) {
    asm volatile("mma.sync.aligned.m16n8k16.row.col.f32.bf16.bf16.f32 "
                 "{%0, %1, %2, %3}, {%4, %5, %6, %7}, {%8, %9}, {%0, %1, %2, %3};"
                 : "+f"(d[0]), "+f"(d[1]), "+f"(d[2]), "+f"(d[3])
                 : "r"(a0), "r"(a1), "r"(a2), "r"(a3), "r"(b0), "r"(b1));
}

#define SW128(o) ((o) ^ (((o) >> 3) & 0x70))
#define ZERO_BLOCKS ((MAX_NODES + 255) / 256)

// ---------------- setup: zero deg/hist/commit + compute W ----------------
__global__ void setup_k(const float* __restrict__ basis, const float* __restrict__ coeff, int N) {
    int b = blockIdx.x;
    if (b < ZERO_BLOCKS) {
        int i = b * 256 + threadIdx.x;
        if (i < N) g_deg[i] = 0.f;
        if (b == 0 && threadIdx.x < N_REL) {
            g_hist[threadIdx.x] = 0;
            g_commit[threadIdx.x] = 0;
        }
        return;
    }
    int r = b - ZERO_BLOCKS;  // 0..N_REL-1
    __shared__ float c[N_BASES];
    if (threadIdx.x < N_BASES) c[threadIdx.x] = coeff[r * N_BASES + threadIdx.x];
    __syncthreads();
    for (int idx = threadIdx.x; idx < IN_F * OUT_F; idx += blockDim.x) {
        float acc = 0.f;
        #pragma unroll
        for (int bb = 0; bb < N_BASES; bb++)
            acc += c[bb] * basis[bb * IN_F * OUT_F + idx];
        int i = idx / OUT_F, o = idx % OUT_F;
        g_Wbf[r * IN_F * OUT_F + o * IN_F + i] = __float2bfloat16(acc);  // store W^T
    }
}

__global__ void hist_deg_k(const int* __restrict__ rel, const int* __restrict__ recv, int E) {
    __shared__ int h[N_REL];
    if (threadIdx.x < N_REL) h[threadIdx.x] = 0;
    __syncthreads();
    for (int e = blockIdx.x * blockDim.x + threadIdx.x; e < E; e += gridDim.x * blockDim.x) {
        atomicAdd(&h[rel[e]], 1);
        atomicAdd(&g_deg[recv[e]], 1.f);
    }
    __syncthreads();
    if (threadIdx.x < N_REL) atomicAdd(&g_hist[threadIdx.x], h[threadIdx.x]);
}

// scatter with per-block local prefix of g_hist (no separate prefix kernel)
__global__ void scatter_k(const int* __restrict__ rel, int E) {
    __shared__ int cnt[N_REL];
    __shared__ int basee[N_REL];
    __shared__ int off_s[N_REL];
    int tid = threadIdx.x;
    if (tid < 32) {
        int h = (tid < N_REL) ? g_hist[tid] : 0;
        int x = h;
        #pragma unroll
        for (int d = 1; d < 32; d <<= 1) {
            int y = __shfl_up_sync(0xffffffffu, x, d);
            if (tid >= d) x += y;
        }
        if (tid < N_REL) off_s[tid] = x - h;  // exclusive prefix
        cnt[tid < N_REL ? tid : 0] = 0;
    }
    __syncthreads();
    if (tid < N_REL) cnt[tid] = 0;
    __syncthreads();

    int chunk = (E + gridDim.x - 1) / gridDim.x;
    int s = blockIdx.x * chunk;
    int e_end = min(E, s + chunk);
    for (int i = s + tid; i < e_end; i += blockDim.x)
        atomicAdd(&cnt[rel[i]], 1);
    __syncthreads();
    if (tid < N_REL)
        basee[tid] = off_s[tid] + atomicAdd(&g_commit[tid], cnt[tid]);
    __syncthreads();
    if (tid < N_REL) cnt[tid] = 0;
    __syncthreads();
    for (int i = s + tid; i < e_end; i += blockDim.x) {
        int r = rel[i];
        int p = atomicAdd(&cnt[r], 1);
        g_sorted[basee[r] + p] = i;
    }
}

// ---------------- self term (fp32) + inv_deg fused ----------------
__device__ __forceinline__ void gemm_core(const float (&Xs)[TE][IN_F],
                                          const float (&Ws)[IN_F][OUT_F],
                                          int row0, int col0, int sw_x,
                                          unsigned long long (&acc)[4][4]) {
    #pragma unroll
    for (int i = 0; i < 4; i++)
        #pragma unroll
        for (int j = 0; j < 4; j++) acc[i][j] = 0ull;

    for (int k = 0; k < IN_F; k += 4) {
        float4 a[4];
        #pragma unroll
        for (int r4 = 0; r4 < 4; r4++)
            a[r4] = ((const float4*)Xs[row0 + r4])[(k >> 2) ^ sw_x];
        #pragma unroll
        for (int u = 0; u < 4; u++) {
            float4 b0 = *(const float4*)&Ws[k + u][col0];
            float4 b1 = *(const float4*)&Ws[k + u][col0 + 4];
            unsigned long long bp0 = f2pack(b0.x, b0.y);
            unsigned long long bp1 = f2pack(b0.z, b0.w);
            unsigned long long bp2 = f2pack(b1.x, b1.y);
            unsigned long long bp3 = f2pack(b1.z, b1.w);
            #pragma unroll
            for (int r4 = 0; r4 < 4; r4++) {
                float av = (u == 0) ? a[r4].x : (u == 1) ? a[r4].y : (u == 2) ? a[r4].z : a[r4].w;
                unsigned long long ap = f2pack(av, av);
                acc[r4][0] = ffma2(ap, bp0, acc[r4][0]);
                acc[r4][1] = ffma2(ap, bp1, acc[r4][1]);
                acc[r4][2] = ffma2(ap, bp2, acc[r4][2]);
                acc[r4][3] = ffma2(ap, bp3, acc[r4][3]);
            }
        }
    }
}

__global__ void __launch_bounds__(256) self_gemm_k(const float* __restrict__ nf,
                                                   const float* __restrict__ sw,
                                                   const float* __restrict__ bias,
                                                   float* __restrict__ out, int N) {
    __shared__ float Xs[TE][IN_F];
    __shared__ float Ws[IN_F][OUT_F];
    int tid = threadIdx.x;
    int base = blockIdx.x * TE;
    int nR = min(TE, N - base);

    // fused inv_deg for this block's rows (consumed by the later edge kernel)
    if (tid < TE && tid < nR)
        g_inv[base + tid] = 1.f / fmaxf(g_deg[base + tid], 1.f);

    {
        const float4* s4 = (const float4*)sw;
        float4* d4 = (float4*)&Ws[0][0];
        for (int i = tid; i < IN_F * OUT_F / 4; i += blockDim.x) d4[i] = s4[i];
    }
    {
        int row = tid & (TE - 1);
        int half = tid >> 7;
        if (row < nR) {
            const float4* src = (const float4*)nf + (long long)(base + row) * (IN_F / 4) + half * 8;
            float4* dst = (float4*)Xs[row];
            int swz = (row >> 2) & 3;
            #pragma unroll
            for (int c = 0; c < 8; c++) dst[(half * 8 + c) ^ swz] = src[c];
        }
    }
    __syncthreads();

    int tx = tid & 7, ty = tid >> 3;
    int row0 = ty * 4, col0 = tx * 8;
    unsigned long long acc[4][4];
    gemm_core(Xs, Ws, row0, col0, ty & 3, acc);

    float4 bias0 = *(const float4*)&bias[col0];
    float4 bias1 = *(const float4*)&bias[col0 + 4];
    #pragma unroll
    for (int r4 = 0; r4 < 4; r4++) {
        int row = row0 + r4;
        if (row < nR) {
            float v[8];
            f2unpack(acc[r4][0], v[0], v[1]);
            f2unpack(acc[r4][1], v[2], v[3]);
            f2unpack(acc[r4][2], v[4], v[5]);
            f2unpack(acc[r4][3], v[6], v[7]);
            float4 o0 = make_float4(v[0] + bias0.x, v[1] + bias0.y, v[2] + bias0.z, v[3] + bias0.w);
            float4 o1 = make_float4(v[4] + bias1.x, v[5] + bias1.y, v[6] + bias1.z, v[7] + bias1.w);
            float* p = out + (long long)(base + row) * OUT_F + col0;
            *(float4*)p = o0;
            *(float4*)(p + 4) = o1;
        }
    }
}

// ---------------- edge messages via mma.sync bf16 (HMMA) ----------------
// D[128 edges, 64 out] = A(bf16 SW128) @ W_r^T. Epilogue: stage D in SMEM (reusing
// the A/B region), then red.global.add.v4 scaled by inv_deg — halves REDG lane-ops
// vs red.v2-from-fragments.
#define DRS 68   // padded row stride (floats) for D staging: conflict-free STS
__global__ void __launch_bounds__(128, 4)
edge_mma_k(const float* __restrict__ nf,
           const int* __restrict__ senders,
           const int* __restrict__ receivers,
           float* __restrict__ out) {
    __shared__ __align__(128) uint8_t sAB[TE * 128 + OUT_F * 128];  // A:16KB, B:8KB; reused for D
    __shared__ int   s_rc[TE];
    __shared__ float s_inv[TE];
    __shared__ int   s_h[N_REL];    // per-relation edge counts
    __shared__ int   s_ti[N_REL];   // inclusive prefix of per-relation tile counts
    __shared__ int   s_off[N_REL];  // exclusive prefix of edge counts

    int tid  = threadIdx.x;
    int w    = tid >> 5;
    int lane = tid & 31;
    int b    = blockIdx.x;

    // local 32-wide scan of g_hist (replaces the prefix kernel)
    if (tid < 32) {
        int h = (tid < N_REL) ? g_hist[tid] : 0;
        int t = (h + TE - 1) / TE;
        int xh = h, xt = t;
        #pragma unroll
        for (int d = 1; d < 32; d <<= 1) {
            int yh = __shfl_up_sync(0xffffffffu, xh, d);
            int yt = __shfl_up_sync(0xffffffffu, xt, d);
            if (tid >= d) { xh += yh; xt += yt; }
        }
        if (tid < N_REL) {
            s_h[tid]   = h;
            s_off[tid] = xh - h;
            s_ti[tid]  = xt;      // inclusive tiles
        }
    }
    __syncthreads();

    if (b >= s_ti[N_REL - 1]) return;
    int r = 0;
    while (b >= s_ti[r]) r++;
    int tiles_r  = (s_h[r] + TE - 1) / TE;
    int tile_idx = b - (s_ti[r] - tiles_r);
    int base     = s_off[r] + tile_idx * TE;
    int nE       = min(TE, s_off[r] + s_h[r] - base);

    uint32_t sA = smem_u32(sAB);
    uint32_t sB = sA + TE * 128;

    // Stage B = W_r^T bf16 (64 rows x 128B), SW128-swizzled
    {
        const uint4* wsrc = (const uint4*)(g_Wbf + (size_t)r * IN_F * OUT_F);
        #pragma unroll
        for (int i = tid; i < 512; i += 128) {
            uint4 v = wsrc[i];
            uint32_t off = (uint32_t)i * 16u;
            sts128(sB + SW128(off), v.x, v.y, v.z, v.w);
        }
    }

    // Gather A: thread tid owns edge-row tid; zero-fill rows >= nE.
    {
        uint32_t rowbase = (uint32_t)tid * 128u;
        if (tid < nE) {
            int e = g_sorted[base + tid];
            int s = senders[e];
            int rc = receivers[e];
            s_rc[tid]  = rc;
            s_inv[tid] = g_inv[rc];
            const float4* src = (const float4*)(nf + (size_t)s * IN_F);
            #pragma unroll
            for (int c = 0; c < 8; c++) {
                float4 f0 = src[2 * c];
                float4 f1 = src[2 * c + 1];
                uint32_t p0 = bf2pack(f0.x, f0.y);
                uint32_t p1 = bf2pack(f0.z, f0.w);
                uint32_t p2 = bf2pack(f1.x, f1.y);
                uint32_t p3 = bf2pack(f1.z, f1.w);
                uint32_t off = rowbase + (uint32_t)c * 16u;
                sts128(sA + SW128(off), p0, p1, p2, p3);
            }
        } else {
            #pragma unroll
            for (int c = 0; c < 8; c++) {
                uint32_t off = rowbase + (uint32_t)c * 16u;
                sts128(sA + SW128(off), 0u, 0u, 0u, 0u);
            }
        }
    }
    __syncthreads();

    // MMA mainloop: 2 m-tiles x 8 n-tiles x 4 k-steps of m16n8k16
    float acc[2][8][4];
    #pragma unroll
    for (int mt = 0; mt < 2; mt++)
        #pragma unroll
        for (int j = 0; j < 8; j++)
            #pragma unroll
            for (int q = 0; q < 4; q++) acc[mt][j][q] = 0.f;

    #pragma unroll
    for (int k = 0; k < 4; k++) {
        uint32_t a[2][4];
        #pragma unroll
        for (int mt = 0; mt < 2; mt++) {
            uint32_t row = (uint32_t)(w * 32 + mt * 16 + (((lane >> 3) & 1) << 3) + (lane & 7));
            uint32_t kb  = (uint32_t)(32 * k + (((lane >> 4) & 1) << 4));
            uint32_t off = row * 128u + kb;
            ldm_x4(a[mt][0], a[mt][1], a[mt][2], a[mt][3], sA + SW128(off));
        }
        uint32_t bf[8][2];
        #pragma unroll
        for (int jp = 0; jp < 4; jp++) {
            uint32_t jl   = (uint32_t)((lane >> 4) & 1);
            uint32_t half = (uint32_t)((lane >> 3) & 1);
            uint32_t rowb = (uint32_t)(8 * (2 * jp + jl) + (lane & 7));
            uint32_t kb   = (uint32_t)(32 * k + 16 * half);
            uint32_t off  = rowb * 128u + kb;
            ldm_x4(bf[2 * jp][0], bf[2 * jp][1], bf[2 * jp + 1][0], bf[2 * jp + 1][1],
                   sB + SW128(off));
        }
        #pragma unroll
        for (int mt = 0; mt < 2; mt++)
            #pragma unroll
            for (int j = 0; j < 8; j++)
                mma_bf16(acc[mt][j], a[mt][0], a[mt][1], a[mt][2], a[mt][3],
                         bf[j][0], bf[j][1]);
    }

    // Epilogue: stage D via SMEM (2 passes x 64 rows), scatter with red.v4
    __syncthreads();
    float* sD = (float*)sAB;  // 64 rows x DRS floats = 17408B <= 24KB
    int g  = lane >> 2;
    int tg = lane & 3;
    #pragma unroll
    for (int p = 0; p < 2; p++) {
        if ((w >> 1) == p) {
            int wl = w & 1;
            #pragma unroll
            for (int mt = 0; mt < 2; mt++) {
                int rl = wl * 32 + mt * 16 + g;   // local row in [0,64)
                #pragma unroll
                for (int j = 0; j < 8; j++) {
                    *(float2*)&sD[rl * DRS + 8 * j + 2 * tg] =
                        make_float2(acc[mt][j][0], acc[mt][j][1]);
                    *(float2*)&sD[(rl + 8) * DRS + 8 * j + 2 * tg] =
                        make_float2(acc[mt][j][2], acc[mt][j][3]);
                }
            }
        }
        __syncthreads();
        int rl   = tid >> 1;
        int half = tid & 1;
        int row  = p * 64 + rl;
        if (row < nE) {
            int rc = s_rc[row];
            float inv = s_inv[row];
            float* po = out + (size_t)rc * OUT_F + half * 32;
            const float* src = &sD[rl * DRS + half * 32];
            #pragma unroll
            for (int c = 0; c < 8; c++) {
                float4 v = *(const float4*)&src[4 * c];
                red4(po + 4 * c, v.x * inv, v.y * inv, v.z * inv, v.w * inv);
            }
        }
        __syncthreads();
    }
}

// ---------------- launch ----------------
extern "C" void kernel_launch(void* const* d_in, const int* in_sizes, int n_in,
                              void* d_out, int out_size) {
    const float* node_features = (const float*)d_in[0];
    const int*   senders       = (const int*)d_in[1];
    const int*   receivers     = (const int*)d_in[2];
    const int*   rel_types     = (const int*)d_in[3];
    const float* basis         = (const float*)d_in[4];
    const float* coeff         = (const float*)d_in[5];
    const float* self_weight   = (const float*)d_in[6];
    const float* bias          = (const float*)d_in[7];
    float* out = (float*)d_out;

    int N = in_sizes[0] / IN_F;
    int E = in_sizes[1];
    if (N > MAX_NODES) N = MAX_NODES;
    if (E > MAX_EDGES) E = MAX_EDGES;

    setup_k<<<ZERO_BLOCKS + N_REL, 256>>>(basis, coeff, N);
    hist_deg_k<<<512, 256>>>(rel_types, receivers, E);
    scatter_k<<<512, 256>>>(rel_types, E);
    self_gemm_k<<<(N + TE - 1) / TE, 256>>>(node_features, self_weight, bias, out, N);

    int max_tiles = (E + TE - 1) / TE + N_REL;
    edge_mma_k<<<max_tiles, 128>>>(node_features, senders, receivers, out);
}

// round 8
// speedup vs baseline: 1.4167x; 1.4167x over previous
#include <cuda_runtime.h>
#include <cuda_bf16.h>
#include <cstdint>

#define N_REL   32
#define N_BASES 30
#define IN_F    64
#define OUT_F   64
#define MAX_NODES 100000
#define MAX_EDGES 1000000
#define TE      128   // rows per tile

// ---------------- device scratch (static, allocation-free) ----------------
__device__ __nv_bfloat16  g_Wbf[N_REL * OUT_F * IN_F];   // bf16 W^T per relation: [r][o][i]
__device__ __nv_bfloat16  g_SWhi[OUT_F * IN_F];          // self_weight^T hi
__device__ __nv_bfloat16  g_SWlo[OUT_F * IN_F];          // self_weight^T lo (residual)
__device__ float g_deg[MAX_NODES];
__device__ float g_inv[MAX_NODES];
__device__ int   g_hist[N_REL];
__device__ int   g_commit[N_REL];
__device__ int   g_sorted[MAX_EDGES];

// ---------------- helpers ----------------
__device__ __forceinline__ uint32_t smem_u32(const void* p) {
    uint32_t a;
    asm("{ .reg .u64 t; cvta.to.shared.u64 t, %1; cvt.u32.u64 %0, t; }" : "=r"(a) : "l"(p));
    return a;
}
__device__ __forceinline__ uint32_t bf2pack(float lo, float hi) {
    uint32_t r;
    asm("cvt.rn.bf16x2.f32 %0, %1, %2;" : "=r"(r) : "f"(hi), "f"(lo));
    return r;
}
__device__ __forceinline__ void sts128(uint32_t addr, uint32_t a, uint32_t b, uint32_t c, uint32_t d) {
    asm volatile("st.shared.v4.b32 [%0], {%1, %2, %3, %4};" :: "r"(addr), "r"(a), "r"(b), "r"(c), "r"(d) : "memory");
}
__device__ __forceinline__ void red2(float* p, float a, float b) {
    asm volatile("red.global.add.v2.f32 [%0], {%1, %2};" :: "l"(p), "f"(a), "f"(b) : "memory");
}
__device__ __forceinline__ void ldm_x4(uint32_t& r0, uint32_t& r1, uint32_t& r2, uint32_t& r3,
                                       uint32_t addr) {
    asm volatile("ldmatrix.sync.aligned.m8n8.x4.shared.b16 {%0, %1, %2, %3}, [%4];"
                 : "=r"(r0), "=r"(r1), "=r"(r2), "=r"(r3) : "r"(addr));
}
__device__ __forceinline__ void mma_bf16(float* d, uint32_t a0, uint32_t a1, uint32_t a2,
                                         uint32_t a3, uint32_t b0, uint32_t b1) {
    asm volatile("mma.sync.aligned.m16n8k16.row.col.f32.bf16.bf16.f32 "
                 "{%0, %1, %2, %3}, {%4, %5, %6, %7}, {%8, %9}, {%0, %1, %2, %3};"
                 : "+f"(d[0]), "+f"(d[1]), "+f"(d[2]), "+f"(d[3])
                 : "r"(a0), "r"(a1), "r"(a2), "r"(a3), "r"(b0), "r"(b1));
}

#define SW128(o) ((o) ^ (((o) >> 3) & 0x70))
#define ZERO_BLOCKS ((MAX_NODES + 255) / 256)

// One MMA pass over a 128x64 @ 64x64 tile pair; accumulates into acc.
__device__ __forceinline__ void mma_tile_pass(uint32_t sA, uint32_t sB, int w, int lane,
                                              float (&acc)[2][8][4]) {
    #pragma unroll
    for (int k = 0; k < 4; k++) {
        uint32_t a[2][4];
        #pragma unroll
        for (int mt = 0; mt < 2; mt++) {
            uint32_t row = (uint32_t)(w * 32 + mt * 16 + (((lane >> 3) & 1) << 3) + (lane & 7));
            uint32_t kb  = (uint32_t)(32 * k + (((lane >> 4) & 1) << 4));
            ldm_x4(a[mt][0], a[mt][1], a[mt][2], a[mt][3], sA + SW128(row * 128u + kb));
        }
        uint32_t bf[8][2];
        #pragma unroll
        for (int jp = 0; jp < 4; jp++) {
            uint32_t jl   = (uint32_t)((lane >> 4) & 1);
            uint32_t half = (uint32_t)((lane >> 3) & 1);
            uint32_t rowb = (uint32_t)(8 * (2 * jp + jl) + (lane & 7));
            uint32_t kb   = (uint32_t)(32 * k + 16 * half);
            ldm_x4(bf[2 * jp][0], bf[2 * jp][1], bf[2 * jp + 1][0], bf[2 * jp + 1][1],
                   sB + SW128(rowb * 128u + kb));
        }
        #pragma unroll
        for (int mt = 0; mt < 2; mt++)
            #pragma unroll
            for (int j = 0; j < 8; j++)
                mma_bf16(acc[mt][j], a[mt][0], a[mt][1], a[mt][2], a[mt][3],
                         bf[j][0], bf[j][1]);
    }
}

// ---------------- setup: zero deg/hist + W_r bf16^T + self_weight hi/lo split ----------------
__global__ void setup_k(const float* __restrict__ basis, const float* __restrict__ coeff,
                        const float* __restrict__ sw, int N) {
    int b = blockIdx.x;
    if (b < ZERO_BLOCKS) {
        int i = b * 256 + threadIdx.x;
        if (i < N) g_deg[i] = 0.f;
        if (b == 0 && threadIdx.x < N_REL) {
            g_hist[threadIdx.x] = 0;
            g_commit[threadIdx.x] = 0;
        }
        return;
    }
    if (b == ZERO_BLOCKS + N_REL) {
        // split self_weight^T into bf16 hi + lo
        for (int idx = threadIdx.x; idx < IN_F * OUT_F; idx += blockDim.x) {
            int i = idx / OUT_F, o = idx % OUT_F;
            float x = sw[idx];
            __nv_bfloat16 h = __float2bfloat16(x);
            float lo = x - __bfloat162float(h);
            g_SWhi[o * IN_F + i] = h;
            g_SWlo[o * IN_F + i] = __float2bfloat16(lo);
        }
        return;
    }
    int r = b - ZERO_BLOCKS;  // 0..N_REL-1
    __shared__ float c[N_BASES];
    if (threadIdx.x < N_BASES) c[threadIdx.x] = coeff[r * N_BASES + threadIdx.x];
    __syncthreads();
    for (int idx = threadIdx.x; idx < IN_F * OUT_F; idx += blockDim.x) {
        float acc = 0.f;
        #pragma unroll
        for (int bb = 0; bb < N_BASES; bb++)
            acc += c[bb] * basis[bb * IN_F * OUT_F + idx];
        int i = idx / OUT_F, o = idx % OUT_F;
        g_Wbf[r * IN_F * OUT_F + o * IN_F + i] = __float2bfloat16(acc);  // W^T
    }
}

__global__ void hist_deg_k(const int* __restrict__ rel, const int* __restrict__ recv, int E) {
    __shared__ int h[N_REL];
    if (threadIdx.x < N_REL) h[threadIdx.x] = 0;
    __syncthreads();
    for (int e = blockIdx.x * blockDim.x + threadIdx.x; e < E; e += gridDim.x * blockDim.x) {
        atomicAdd(&h[rel[e]], 1);
        atomicAdd(&g_deg[recv[e]], 1.f);
    }
    __syncthreads();
    if (threadIdx.x < N_REL) atomicAdd(&g_hist[threadIdx.x], h[threadIdx.x]);
}

// scatter with per-block local prefix of g_hist (no separate prefix kernel)
__global__ void scatter_k(const int* __restrict__ rel, int E) {
    __shared__ int cnt[N_REL];
    __shared__ int basee[N_REL];
    __shared__ int off_s[N_REL];
    int tid = threadIdx.x;
    if (tid < 32) {
        int h = (tid < N_REL) ? g_hist[tid] : 0;
        int x = h;
        #pragma unroll
        for (int d = 1; d < 32; d <<= 1) {
            int y = __shfl_up_sync(0xffffffffu, x, d);
            if (tid >= d) x += y;
        }
        if (tid < N_REL) off_s[tid] = x - h;  // exclusive prefix
    }
    __syncthreads();
    if (tid < N_REL) cnt[tid] = 0;
    __syncthreads();

    int chunk = (E + gridDim.x - 1) / gridDim.x;
    int s = blockIdx.x * chunk;
    int e_end = min(E, s + chunk);
    for (int i = s + tid; i < e_end; i += blockDim.x)
        atomicAdd(&cnt[rel[i]], 1);
    __syncthreads();
    if (tid < N_REL)
        basee[tid] = off_s[tid] + atomicAdd(&g_commit[tid], cnt[tid]);
    __syncthreads();
    if (tid < N_REL) cnt[tid] = 0;
    __syncthreads();
    for (int i = s + tid; i < e_end; i += blockDim.x) {
        int r = rel[i];
        int p = atomicAdd(&cnt[r], 1);
        g_sorted[basee[r] + p] = i;
    }
}

// ---------------- self term via bf16-split HMMA: out = X@SW + bias (fp32 accuracy) ----------------
// acc = Ah*Bh + Ah*Bl + Al*Bh ; neglected Al*Bl ~ 2^-18 relative.
__global__ void __launch_bounds__(128) self_hmma_k(const float* __restrict__ nf,
                                                   const float* __restrict__ bias,
                                                   float* __restrict__ out, int N) {
    __shared__ __align__(128) uint8_t sm[TE * 128 * 2 + OUT_F * 128 * 2];  // Ah,Al,Bh,Bl = 48KB
    int tid  = threadIdx.x;
    int w    = tid >> 5;
    int lane = tid & 31;
    int base = blockIdx.x * TE;
    int nR   = min(TE, N - base);

    uint32_t sAh = smem_u32(sm);
    uint32_t sAl = sAh + TE * 128;
    uint32_t sBh = sAl + TE * 128;
    uint32_t sBl = sBh + OUT_F * 128;

    // fused inv_deg for this block's rows (consumed by the edge kernel)
    if (tid < nR)
        g_inv[base + tid] = 1.f / fmaxf(g_deg[base + tid], 1.f);

    // stage B hi/lo (each 8KB = 512 x 16B)
    {
        const uint4* bh = (const uint4*)g_SWhi;
        const uint4* bl = (const uint4*)g_SWlo;
        #pragma unroll
        for (int i = tid; i < 512; i += 128) {
            uint32_t off = SW128((uint32_t)i * 16u);
            uint4 vh = bh[i];
            uint4 vl = bl[i];
            sts128(sBh + off, vh.x, vh.y, vh.z, vh.w);
            sts128(sBl + off, vl.x, vl.y, vl.z, vl.w);
        }
    }

    // load + split A row `tid`
    {
        uint32_t rowbase = (uint32_t)tid * 128u;
        if (tid < nR) {
            const float4* src = (const float4*)(nf + (size_t)(base + tid) * IN_F);
            #pragma unroll
            for (int c = 0; c < 4; c++) {
                float4 f0 = src[4 * c + 0];
                float4 f1 = src[4 * c + 1];
                float4 f2 = src[4 * c + 2];
                float4 f3 = src[4 * c + 3];
                float hf[16], lf[16];
                const float* fv = &f0.x;  // f0..f3 contiguous on stack
                float tmp[16] = {f0.x,f0.y,f0.z,f0.w, f1.x,f1.y,f1.z,f1.w,
                                 f2.x,f2.y,f2.z,f2.w, f3.x,f3.y,f3.z,f3.w};
                (void)fv;
                #pragma unroll
                for (int q = 0; q < 16; q++) {
                    __nv_bfloat16 h = __float2bfloat16(tmp[q]);
                    hf[q] = __bfloat162float(h);
                    lf[q] = tmp[q] - hf[q];
                }
                uint32_t offA = rowbase + (uint32_t)c * 32u;
                sts128(sAh + SW128(offA),
                       bf2pack(hf[0], hf[1]), bf2pack(hf[2], hf[3]),
                       bf2pack(hf[4], hf[5]), bf2pack(hf[6], hf[7]));
                sts128(sAh + SW128(offA + 16u),
                       bf2pack(hf[8], hf[9]), bf2pack(hf[10], hf[11]),
                       bf2pack(hf[12], hf[13]), bf2pack(hf[14], hf[15]));
                sts128(sAl + SW128(offA),
                       bf2pack(lf[0], lf[1]), bf2pack(lf[2], lf[3]),
                       bf2pack(lf[4], lf[5]), bf2pack(lf[6], lf[7]));
                sts128(sAl + SW128(offA + 16u),
                       bf2pack(lf[8], lf[9]), bf2pack(lf[10], lf[11]),
                       bf2pack(lf[12], lf[13]), bf2pack(lf[14], lf[15]));
            }
        } else {
            #pragma unroll
            for (int c = 0; c < 8; c++) {
                uint32_t off = rowbase + (uint32_t)c * 16u;
                sts128(sAh + SW128(off), 0u, 0u, 0u, 0u);
                sts128(sAl + SW128(off), 0u, 0u, 0u, 0u);
            }
        }
    }
    __syncthreads();

    float acc[2][8][4];
    #pragma unroll
    for (int mt = 0; mt < 2; mt++)
        #pragma unroll
        for (int j = 0; j < 8; j++)
            #pragma unroll
            for (int q = 0; q < 4; q++) acc[mt][j][q] = 0.f;

    mma_tile_pass(sAh, sBh, w, lane, acc);
    mma_tile_pass(sAh, sBl, w, lane, acc);
    mma_tile_pass(sAl, sBh, w, lane, acc);

    // epilogue: bias + direct store
    int g  = lane >> 2;
    int tg = lane & 3;
    float2 bv[8];
    #pragma unroll
    for (int j = 0; j < 8; j++) bv[j] = *(const float2*)&bias[8 * j + 2 * tg];
    #pragma unroll
    for (int mt = 0; mt < 2; mt++) {
        int r1 = base + w * 32 + mt * 16 + g;
        int r2 = r1 + 8;
        #pragma unroll
        for (int j = 0; j < 8; j++) {
            if (r1 < N)
                *(float2*)(out + (size_t)r1 * OUT_F + 8 * j + 2 * tg) =
                    make_float2(acc[mt][j][0] + bv[j].x, acc[mt][j][1] + bv[j].y);
            if (r2 < N)
                *(float2*)(out + (size_t)r2 * OUT_F + 8 * j + 2 * tg) =
                    make_float2(acc[mt][j][2] + bv[j].x, acc[mt][j][3] + bv[j].y);
        }
    }
}

// ---------------- edge messages via mma.sync bf16 (HMMA), R5 epilogue ----------------
__global__ void __launch_bounds__(128, 4)
edge_mma_k(const float* __restrict__ nf,
           const int* __restrict__ senders,
           const int* __restrict__ receivers,
           float* __restrict__ out) {
    __shared__ __align__(128) uint8_t sAB[TE * 128 + OUT_F * 128];  // A:16KB, B:8KB
    __shared__ int   s_rc[TE];
    __shared__ float s_inv[TE];
    __shared__ int   s_h[N_REL];
    __shared__ int   s_ti[N_REL];
    __shared__ int   s_off[N_REL];

    int tid  = threadIdx.x;
    int w    = tid >> 5;
    int lane = tid & 31;
    int b    = blockIdx.x;

    // local 32-wide scan of g_hist (replaces prefix kernel)
    if (tid < 32) {
        int h = (tid < N_REL) ? g_hist[tid] : 0;
        int t = (h + TE - 1) / TE;
        int xh = h, xt = t;
        #pragma unroll
        for (int d = 1; d < 32; d <<= 1) {
            int yh = __shfl_up_sync(0xffffffffu, xh, d);
            int yt = __shfl_up_sync(0xffffffffu, xt, d);
            if (tid >= d) { xh += yh; xt += yt; }
        }
        if (tid < N_REL) {
            s_h[tid]   = h;
            s_off[tid] = xh - h;
            s_ti[tid]  = xt;
        }
    }
    __syncthreads();

    if (b >= s_ti[N_REL - 1]) return;
    int r = 0;
    while (b >= s_ti[r]) r++;
    int tiles_r  = (s_h[r] + TE - 1) / TE;
    int tile_idx = b - (s_ti[r] - tiles_r);
    int base     = s_off[r] + tile_idx * TE;
    int nE       = min(TE, s_off[r] + s_h[r] - base);

    uint32_t sA = smem_u32(sAB);
    uint32_t sB = sA + TE * 128;

    // stage B = W_r^T bf16
    {
        const uint4* wsrc = (const uint4*)(g_Wbf + (size_t)r * IN_F * OUT_F);
        #pragma unroll
        for (int i = tid; i < 512; i += 128) {
            uint4 v = wsrc[i];
            sts128(sB + SW128((uint32_t)i * 16u), v.x, v.y, v.z, v.w);
        }
    }

    // gather A; zero-fill rows >= nE
    {
        uint32_t rowbase = (uint32_t)tid * 128u;
        if (tid < nE) {
            int e = g_sorted[base + tid];
            int s = senders[e];
            int rc = receivers[e];
            s_rc[tid]  = rc;
            s_inv[tid] = g_inv[rc];
            const float4* src = (const float4*)(nf + (size_t)s * IN_F);
            #pragma unroll
            for (int c = 0; c < 8; c++) {
                float4 f0 = src[2 * c];
                float4 f1 = src[2 * c + 1];
                sts128(sA + SW128(rowbase + (uint32_t)c * 16u),
                       bf2pack(f0.x, f0.y), bf2pack(f0.z, f0.w),
                       bf2pack(f1.x, f1.y), bf2pack(f1.z, f1.w));
            }
        } else {
            #pragma unroll
            for (int c = 0; c < 8; c++)
                sts128(sA + SW128(rowbase + (uint32_t)c * 16u), 0u, 0u, 0u, 0u);
        }
    }
    __syncthreads();

    float acc[2][8][4];
    #pragma unroll
    for (int mt = 0; mt < 2; mt++)
        #pragma unroll
        for (int j = 0; j < 8; j++)
            #pragma unroll
            for (int q = 0; q < 4; q++) acc[mt][j][q] = 0.f;

    mma_tile_pass(sA, sB, w, lane, acc);

    // R5 epilogue: red.v2 direct from fragments, scaled by inv_deg
    int g  = lane >> 2;
    int tg = lane & 3;
    #pragma unroll
    for (int mt = 0; mt < 2; mt++) {
        int r1 = w * 32 + mt * 16 + g;
        int r2 = r1 + 8;
        bool v1 = r1 < nE, v2 = r2 < nE;
        float inv1 = 0.f, inv2 = 0.f;
        int   rc1 = 0, rc2 = 0;
        if (v1) { rc1 = s_rc[r1]; inv1 = s_inv[r1]; }
        if (v2) { rc2 = s_rc[r2]; inv2 = s_inv[r2]; }
        float* p1 = out + (size_t)rc1 * OUT_F + 2 * tg;
        float* p2 = out + (size_t)rc2 * OUT_F + 2 * tg;
        #pragma unroll
        for (int j = 0; j < 8; j++) {
            if (v1) red2(p1 + 8 * j, acc[mt][j][0] * inv1, acc[mt][j][1] * inv1);
            if (v2) red2(p2 + 8 * j, acc[mt][j][2] * inv2, acc[mt][j][3] * inv2);
        }
    }
}

// ---------------- launch ----------------
extern "C" void kernel_launch(void* const* d_in, const int* in_sizes, int n_in,
                              void* d_out, int out_size) {
    const float* node_features = (const float*)d_in[0];
    const int*   senders       = (const int*)d_in[1];
    const int*   receivers     = (const int*)d_in[2];
    const int*   rel_types     = (const int*)d_in[3];
    const float* basis         = (const float*)d_in[4];
    const float* coeff         = (const float*)d_in[5];
    const float* self_weight   = (const float*)d_in[6];
    const float* bias          = (const float*)d_in[7];
    float* out = (float*)d_out;

    int N = in_sizes[0] / IN_F;
    int E = in_sizes[1];
    if (N > MAX_NODES) N = MAX_NODES;
    if (E > MAX_EDGES) E = MAX_EDGES;

    setup_k<<<ZERO_BLOCKS + N_REL + 1, 256>>>(basis, coeff, self_weight, N);
    hist_deg_k<<<512, 256>>>(rel_types, receivers, E);
    scatter_k<<<512, 256>>>(rel_types, E);
    self_hmma_k<<<(N + TE - 1) / TE, 128>>>(node_features, bias, out, N);

    int max_tiles = (E + TE - 1) / TE + N_REL;
    edge_mma_k<<<max_tiles, 128>>>(node_features, senders, receivers, out);
}